// round 1
// baseline (speedup 1.0000x reference)
#include <cuda_runtime.h>
#include <math.h>

#define TRAJ 1000
#define Bn 512
#define Nn 256
#define Fn 1024   // 4*N
#define Hn 2048
#define On 512

// ---- scratch (static __device__ arrays: allocation-free) ----
__device__ float g_traj[TRAJ];
__device__ float g_cgt[TRAJ], g_csq[TRAJ], g_cent[TRAJ];
__device__ float g_sv[1024];           // sorted traj values, padded to 1024 with +inf
__device__ int   g_si[TRAJ];           // original indices of sorted values
__device__ float g_feats[Bn * Fn];     // [512, 1024]
__device__ float g_h[Bn * Hn];         // [512, 2048]
__device__ float g_part[2 * Bn * On];  // split-K partials for GEMM2

// ============================================================
// Kernel 1: serial tent-map trajectory (bitwise IEEE) + prefix tables
// ============================================================
__global__ void setup_kernel(const float* __restrict__ icp, const float* __restrict__ thp) {
    __shared__ float s_traj[TRAJ];
    __shared__ float t1[TRAJ], t2[TRAJ], t3[TRAJ];
    int t = threadIdx.x;

    if (t == 0) {
        float th = *thp;
        float c  = *icp;
        float omt = 1.0f - th;     // exact
        s_traj[0] = c;
        for (int i = 1; i < TRAJ; i++) {
            // IEEE-RN division regardless of fast-math flags: the map is chaotic,
            // any non-IEEE division would diverge from the reference trajectory.
            float a = __fdiv_rn(c, th);
            float b = __fdiv_rn(1.0f - c, omt);
            c = (c < th) ? a : b;
            s_traj[i] = c;
        }
    }
    __syncthreads();

    if (t < TRAJ) {
        float v = s_traj[t];
        g_traj[t] = v;
        t1[t] = (v > 0.5f) ? 1.0f : 0.0f;
        t2[t] = v * v;
        t3[t] = v * log2f(v + 1e-10f);
    }
    __syncthreads();

    if (t == 0) {
        // exclusive cumsums, sequential order (matches jnp.cumsum closely;
        // these enter the output linearly so ~1e-6 drift is fine)
        float s1 = 0.f, s2 = 0.f, s3 = 0.f;
        for (int i = 0; i < TRAJ; i++) {
            g_cgt[i] = s1; g_csq[i] = s2; g_cent[i] = s3;
            s1 += t1[i]; s2 += t2[i]; s3 += t3[i];
        }
    }
}

// ============================================================
// Kernel 2: stable rank-sort of the 1000 trajectory values
// ============================================================
__global__ void sort_kernel() {
    __shared__ float s[TRAJ];
    int k = blockIdx.x * 128 + threadIdx.x;
    for (int j = threadIdx.x; j < TRAJ; j += 128) s[j] = g_traj[j];
    __syncthreads();
    if (k < TRAJ) {
        float v = s[k];
        int r = 0;
#pragma unroll 4
        for (int j = 0; j < TRAJ; j++) {
            float u = s[j];
            r += (u < v) || (u == v && j < k);   // stable: ties broken by index
        }
        g_sv[r] = v;
        g_si[r] = k;
    } else if (k < 1024) {
        g_sv[k] = __int_as_float(0x7f800000);    // +inf pad for branchless search
    }
}

// ============================================================
// Kernel 3: features via binary-search argmin (exact first-min semantics)
// ============================================================
__global__ void features_kernel(const float* __restrict__ X) {
    __shared__ float s_sv[1024];
    __shared__ int   s_si[TRAJ];
    __shared__ float s_cgt[TRAJ], s_csq[TRAJ], s_cent[TRAJ];
    int tid = threadIdx.x;
    for (int j = tid; j < 1024; j += 256) s_sv[j] = g_sv[j];
    for (int j = tid; j < TRAJ; j += 256) {
        s_si[j] = g_si[j]; s_cgt[j] = g_cgt[j]; s_csq[j] = g_csq[j]; s_cent[j] = g_cent[j];
    }
    __syncthreads();

    float x = X[blockIdx.x * Nn + tid];

    // branchless lower_bound over padded 1024 array: lo = #elements < x
    int lo = 0;
#pragma unroll
    for (int step = 512; step > 0; step >>= 1)
        if (s_sv[lo + step - 1] < x) lo += step;

    const float INF = __int_as_float(0x7f800000);
    float dl = (lo > 0)    ? fabsf(x - s_sv[lo - 1]) : INF;
    float dr = (lo < TRAJ) ? fabsf(x - s_sv[lo])     : INF;
    float d = fminf(dl, dr);

    // rounded distance is monotone along sorted order on each side of x,
    // so all global minimizers form contiguous runs adjacent to lo-1 / lo.
    // Take the min ORIGINAL index over those runs == jnp.argmin first-min.
    int mi = 0x7fffffff;
    if (dl == d)
        for (int k = lo - 1; k >= 0 && fabsf(x - s_sv[k]) == d; --k) mi = min(mi, s_si[k]);
    if (dr == d)
        for (int k = lo; k < TRAJ && fabsf(x - s_sv[k]) == d; ++k) mi = min(mi, s_si[k]);

    int idx = mi;
    float tt = (float)idx;
    float ttss = (idx > 0) ? __fdiv_rn(s_cgt[idx], tt) : 0.0f;  // max(tt,1)=tt for idx>=1
    float4 f4 = make_float4(ttss, s_csq[idx], tt, -s_cent[idx]);
    *(float4*)&g_feats[blockIdx.x * Fn + tid * 4] = f4;
}

// ============================================================
// Kernel 4/5: tiled fp32 GEMM, 64x64 tile, 4x4 per thread,
// optional split-K via gridDim.z, fused bias+ReLU epilogue
// ============================================================
template <bool RELU>
__global__ void __launch_bounds__(256)
gemm_kernel(const float* __restrict__ A, const float* __restrict__ B,
            const float* __restrict__ bias, float* __restrict__ C,
            int M, int N, int K) {
    const int BK = 16;
    __shared__ float As[BK][64];
    __shared__ float Bs[BK][64];

    int z    = blockIdx.z;
    int kLen = K / gridDim.z;
    int k0   = z * kLen;
    C += (size_t)z * M * N;

    int t = threadIdx.x;
    int tx = t & 15, ty = t >> 4;
    const float* Ab = A + (size_t)(blockIdx.y * 64) * K + k0;
    const float* Bb = B + (size_t)k0 * N + blockIdx.x * 64;

    int aRow = t >> 2,  aCol = (t & 3) * 4;    // A: 64 rows x 16 k, float4 along k
    int bRow = t >> 4,  bCol = (t & 15) * 4;   // B: 16 k x 64 cols, float4 along n

    float acc[4][4] = {};

    for (int kc = 0; kc < kLen; kc += BK) {
        float4 av = *(const float4*)(Ab + (size_t)aRow * K + kc + aCol);
        float4 bv = *(const float4*)(Bb + (size_t)(kc + bRow) * N + bCol);
        __syncthreads();   // previous tile fully consumed
        As[aCol + 0][aRow] = av.x; As[aCol + 1][aRow] = av.y;
        As[aCol + 2][aRow] = av.z; As[aCol + 3][aRow] = av.w;
        *(float4*)&Bs[bRow][bCol] = bv;
        __syncthreads();
#pragma unroll
        for (int kk = 0; kk < BK; kk++) {
            float4 a = *(const float4*)&As[kk][ty * 4];
            float4 b = *(const float4*)&Bs[kk][tx * 4];
            float aa[4] = {a.x, a.y, a.z, a.w};
            float bb[4] = {b.x, b.y, b.z, b.w};
#pragma unroll
            for (int i = 0; i < 4; i++)
#pragma unroll
                for (int j = 0; j < 4; j++)
                    acc[i][j] = fmaf(aa[i], bb[j], acc[i][j]);
        }
    }

    int row = blockIdx.y * 64 + ty * 4;
    int col = blockIdx.x * 64 + tx * 4;
#pragma unroll
    for (int i = 0; i < 4; i++) {
        float4 v = make_float4(acc[i][0], acc[i][1], acc[i][2], acc[i][3]);
        if (bias) {
            const float4 bi = *(const float4*)&bias[col];
            v.x += bi.x; v.y += bi.y; v.z += bi.z; v.w += bi.w;
        }
        if (RELU) {
            v.x = fmaxf(v.x, 0.f); v.y = fmaxf(v.y, 0.f);
            v.z = fmaxf(v.z, 0.f); v.w = fmaxf(v.w, 0.f);
        }
        *(float4*)&C[(size_t)(row + i) * N + col] = v;
    }
}

// ============================================================
// Kernel 6: combine split-K partials + bias b2 -> d_out
// ============================================================
__global__ void reduce_kernel(const float* __restrict__ b2, float* __restrict__ out) {
    int i = blockIdx.x * 256 + threadIdx.x;
    out[i] = g_part[i] + g_part[Bn * On + i] + b2[i & (On - 1)];
}

// ============================================================
extern "C" void kernel_launch(void* const* d_in, const int* in_sizes, int n_in,
                              void* d_out, int out_size) {
    const float* x  = (const float*)d_in[0];
    const float* W1 = (const float*)d_in[1];
    const float* b1 = (const float*)d_in[2];
    const float* W2 = (const float*)d_in[3];
    const float* b2 = (const float*)d_in[4];
    const float* ic = (const float*)d_in[5];
    const float* th = (const float*)d_in[6];
    float* out = (float*)d_out;

    float *feats, *h, *part;
    cudaGetSymbolAddress((void**)&feats, g_feats);
    cudaGetSymbolAddress((void**)&h,     g_h);
    cudaGetSymbolAddress((void**)&part,  g_part);

    setup_kernel<<<1, 1024>>>(ic, th);
    sort_kernel<<<8, 128>>>();
    features_kernel<<<Bn, Nn>>>(x);
    // h = relu(feats @ W1 + b1): M=512, N=2048, K=1024
    gemm_kernel<true><<<dim3(Hn / 64, Bn / 64, 1), 256>>>(feats, W1, b1, h, Bn, Hn, Fn);
    // partials of h @ W2: M=512, N=512, K=2048, split-K=2 (128 blocks)
    gemm_kernel<false><<<dim3(On / 64, Bn / 64, 2), 256>>>(h, W2, nullptr, part, Bn, On, Hn);
    reduce_kernel<<<(Bn * On) / 256, 256>>>(b2, out);
}

// round 3
// speedup vs baseline: 1.5520x; 1.5520x over previous
#include <cuda_runtime.h>
#include <cuda_bf16.h>
#include <math.h>
#include <stdint.h>

#define TRAJ 1000
#define Bn 512
#define Nn 256
#define Fn 1024   // 4*N
#define Hn 2048
#define On 512

// ================= scratch (static __device__: allocation-free) =================
__device__ float g_traj[TRAJ];
__device__ float g_cgt[TRAJ], g_csq[TRAJ], g_cent[TRAJ];
__device__ float g_sv[1024];
__device__ int   g_si[TRAJ];
__device__ __nv_bfloat16 g_fH[Bn * Fn],  g_fL[Bn * Fn];    // feats hi/lo [512,1024]
__device__ __nv_bfloat16 g_w1h[Hn * Fn], g_w1l[Hn * Fn];   // W1^T hi/lo [2048,1024]
__device__ __nv_bfloat16 g_w2h[On * Hn], g_w2l[On * Hn];   // W2^T hi/lo [512,2048]
__device__ __nv_bfloat16 g_hH[Bn * Hn],  g_hL[Bn * Hn];    // h hi/lo [512,2048]
__device__ float g_part[8 * Bn * On];                      // split-K partials (2M floats)

// ================= helpers =================
__device__ __forceinline__ uint32_t smem_to_u32(const void* p) {
    uint32_t a;
    asm("{ .reg .u64 t; cvta.to.shared.u64 t, %1; cvt.u32.u64 %0, t; }" : "=r"(a) : "l"(p));
    return a;
}
__device__ __forceinline__ void cp_async16(uint32_t dst, const void* src) {
    asm volatile("cp.async.cg.shared.global [%0], [%1], 16;" :: "r"(dst), "l"(src));
}
__device__ __forceinline__ void cp_commit() { asm volatile("cp.async.commit_group;"); }
__device__ __forceinline__ void cp_wait1()  { asm volatile("cp.async.wait_group 1;"); }
__device__ __forceinline__ void cp_wait0()  { asm volatile("cp.async.wait_group 0;"); }

__device__ __forceinline__ void ldm_x4(uint32_t* r, uint32_t addr) {
    asm volatile("ldmatrix.sync.aligned.m8n8.x4.shared.b16 {%0,%1,%2,%3}, [%4];"
                 : "=r"(r[0]), "=r"(r[1]), "=r"(r[2]), "=r"(r[3]) : "r"(addr));
}
__device__ __forceinline__ void ldm_x2(uint32_t* r, uint32_t addr) {
    asm volatile("ldmatrix.sync.aligned.m8n8.x2.shared.b16 {%0,%1}, [%2];"
                 : "=r"(r[0]), "=r"(r[1]) : "r"(addr));
}
__device__ __forceinline__ void mma_bf16(float* c, const uint32_t* a, const uint32_t* b) {
    asm volatile("mma.sync.aligned.m16n8k16.row.col.f32.bf16.bf16.f32 "
                 "{%0,%1,%2,%3}, {%4,%5,%6,%7}, {%8,%9}, {%0,%1,%2,%3};"
                 : "+f"(c[0]), "+f"(c[1]), "+f"(c[2]), "+f"(c[3])
                 : "r"(a[0]), "r"(a[1]), "r"(a[2]), "r"(a[3]), "r"(b[0]), "r"(b[1]));
}
__device__ __forceinline__ void bf16_split(float v, __nv_bfloat16& h, __nv_bfloat16& l) {
    h = __float2bfloat16(v);
    l = __float2bfloat16(v - __bfloat162float(h));
}

// ============================================================
// Kernel 1: serial tent-map trajectory (bitwise IEEE) + prefix tables
// ============================================================
__global__ void setup_kernel(const float* __restrict__ icp, const float* __restrict__ thp) {
    __shared__ float s_traj[TRAJ];
    __shared__ float t1[TRAJ], t2[TRAJ], t3[TRAJ];
    int t = threadIdx.x;
    if (t == 0) {
        float th = *thp, c = *icp, omt = 1.0f - th;
        s_traj[0] = c;
        for (int i = 1; i < TRAJ; i++) {
            float a = __fdiv_rn(c, th);
            float b = __fdiv_rn(1.0f - c, omt);
            c = (c < th) ? a : b;
            s_traj[i] = c;
        }
    }
    __syncthreads();
    if (t < TRAJ) {
        float v = s_traj[t];
        g_traj[t] = v;
        t1[t] = (v > 0.5f) ? 1.0f : 0.0f;
        t2[t] = v * v;
        t3[t] = v * log2f(v + 1e-10f);
    }
    __syncthreads();
    if (t == 0) {
        float s1 = 0.f, s2 = 0.f, s3 = 0.f;
        for (int i = 0; i < TRAJ; i++) {
            g_cgt[i] = s1; g_csq[i] = s2; g_cent[i] = s3;
            s1 += t1[i]; s2 += t2[i]; s3 += t3[i];
        }
    }
}

// ============================================================
// Kernel 2: stable rank-sort of 1000 traj values
// ============================================================
__global__ void sort_kernel() {
    __shared__ float s[TRAJ];
    int k = blockIdx.x * 128 + threadIdx.x;
    for (int j = threadIdx.x; j < TRAJ; j += 128) s[j] = g_traj[j];
    __syncthreads();
    if (k < TRAJ) {
        float v = s[k];
        int r = 0;
#pragma unroll 4
        for (int j = 0; j < TRAJ; j++) {
            float u = s[j];
            r += (u < v) || (u == v && j < k);
        }
        g_sv[r] = v;
        g_si[r] = k;
    } else if (k < 1024) {
        g_sv[k] = __int_as_float(0x7f800000);
    }
}

// ============================================================
// Kernel 3: features (binary-search argmin), writes bf16 hi/lo
// ============================================================
__global__ void features_kernel(const float* __restrict__ X) {
    __shared__ float s_sv[1024];
    __shared__ int   s_si[TRAJ];
    __shared__ float s_cgt[TRAJ], s_csq[TRAJ], s_cent[TRAJ];
    int tid = threadIdx.x;
    for (int j = tid; j < 1024; j += 256) s_sv[j] = g_sv[j];
    for (int j = tid; j < TRAJ; j += 256) {
        s_si[j] = g_si[j]; s_cgt[j] = g_cgt[j]; s_csq[j] = g_csq[j]; s_cent[j] = g_cent[j];
    }
    __syncthreads();

    float x = X[blockIdx.x * Nn + tid];
    int lo = 0;
#pragma unroll
    for (int step = 512; step > 0; step >>= 1)
        if (s_sv[lo + step - 1] < x) lo += step;

    const float INF = __int_as_float(0x7f800000);
    float dl = (lo > 0)    ? fabsf(x - s_sv[lo - 1]) : INF;
    float dr = (lo < TRAJ) ? fabsf(x - s_sv[lo])     : INF;
    float d = fminf(dl, dr);
    int mi = 0x7fffffff;
    if (dl == d)
        for (int k = lo - 1; k >= 0 && fabsf(x - s_sv[k]) == d; --k) mi = min(mi, s_si[k]);
    if (dr == d)
        for (int k = lo; k < TRAJ && fabsf(x - s_sv[k]) == d; ++k) mi = min(mi, s_si[k]);

    int idx = mi;
    float tt = (float)idx;
    float f[4];
    f[0] = (idx > 0) ? __fdiv_rn(s_cgt[idx], tt) : 0.0f;
    f[1] = s_csq[idx];
    f[2] = tt;
    f[3] = -s_cent[idx];
    size_t o = (size_t)blockIdx.x * Fn + tid * 4;
#pragma unroll
    for (int j = 0; j < 4; j++) bf16_split(f[j], g_fH[o + j], g_fL[o + j]);
}

// ============================================================
// Kernel 4: transpose + bf16 hi/lo split of weights: W[K,N] -> T[N,K]
// ============================================================
__global__ void conv_transpose(const float* __restrict__ W, __nv_bfloat16* __restrict__ Th,
                               __nv_bfloat16* __restrict__ Tl, int K, int N) {
    __shared__ float tile[32][33];
    int n0 = blockIdx.x * 32, k0 = blockIdx.y * 32;
    int tx = threadIdx.x, ty = threadIdx.y;
    for (int j = ty; j < 32; j += 8)
        tile[j][tx] = W[(size_t)(k0 + j) * N + n0 + tx];
    __syncthreads();
    for (int j = ty; j < 32; j += 8) {
        float v = tile[tx][j];
        size_t o = (size_t)(n0 + j) * K + k0 + tx;
        __nv_bfloat16 h, l; bf16_split(v, h, l);
        Th[o] = h; Tl[o] = l;
    }
}

// ============================================================
// Kernel 5: warp-MMA bf16 3-pass GEMM (HMMA via mma.sync, sm_100-safe)
//   part[z][M][Ntot] = Atile @ Btile^T  (A[M,K], B[N,K] K-major, hi/lo)
//   CTA tile 128x128, BK=32, 8 warps (2x4), warp tile 64x32
// ============================================================
#define TS 40                 // smem row stride in bf16 elems (80 B, conflict-free)
#define TILE_E (128 * TS)     // elems per array tile (5120)
#define TILE_B (TILE_E * 2)   // bytes (10240)

__global__ void __launch_bounds__(256, 1)
gemm_mma(const __nv_bfloat16* __restrict__ Ah, const __nv_bfloat16* __restrict__ Al,
         const __nv_bfloat16* __restrict__ Bh, const __nv_bfloat16* __restrict__ Bl,
         float* __restrict__ part, int K, int Ntot, int M) {
    extern __shared__ __nv_bfloat16 sm[];
    uint32_t sb = smem_to_u32(sm);
    int tid = threadIdx.x, wid = tid >> 5, lid = tid & 31;
    int wm = wid >> 2, wn = wid & 3;              // 2 x 4 warp grid

    int m0 = blockIdx.y * 128, n0 = blockIdx.x * 128, z = blockIdx.z;
    int kLen = K / gridDim.z, k0 = z * kLen;
    int nChunks = kLen / 32;

    // per-chunk prefetch: 4 arrays x 128 rows x 4 x 16B, 256 threads x 2 iters
    int pRow = tid >> 2, pI = tid & 3;            // iter adds +64 rows
    size_t gOffA0 = ((size_t)(m0 + pRow) * K + k0 + pI * 8) * 2;
    size_t gOffB0 = ((size_t)(n0 + pRow) * K + k0 + pI * 8) * 2;
    uint32_t sOff0 = (uint32_t)(pRow * TS * 2 + pI * 16);
    size_t rowAdv = (size_t)64 * K * 2;           // +64 rows in bytes

#define PREFETCH(c, b) do {                                                        \
    size_t kb8 = (size_t)(c) * 64;  /* 32 elems * 2B */                            \
    uint32_t base = sb + (uint32_t)(b) * 4 * TILE_B;                               \
    _Pragma("unroll")                                                              \
    for (int it = 0; it < 2; it++) {                                               \
        uint32_t so = base + sOff0 + (uint32_t)it * 64 * TS * 2;                   \
        size_t ga = gOffA0 + kb8 + (size_t)it * rowAdv;                            \
        size_t gb = gOffB0 + kb8 + (size_t)it * rowAdv;                            \
        cp_async16(so + 0 * TILE_B, (const char*)Ah + ga);                         \
        cp_async16(so + 1 * TILE_B, (const char*)Al + ga);                         \
        cp_async16(so + 2 * TILE_B, (const char*)Bh + gb);                         \
        cp_async16(so + 3 * TILE_B, (const char*)Bl + gb);                         \
    }                                                                              \
    cp_commit();                                                                   \
} while (0)

    float acc[4][4][4];
#pragma unroll
    for (int i = 0; i < 4; i++)
#pragma unroll
        for (int j = 0; j < 4; j++)
#pragma unroll
            for (int k = 0; k < 4; k++) acc[i][j][k] = 0.f;

    // ldmatrix lane addressing (byte offsets within an array tile)
    int lr = lid & 7, sub = lid >> 3;             // sub 0..3
    // A x4: matrices (m0-7,k0-7),(m8-15,k0-7),(m0-7,k8-15),(m8-15,k8-15)
    int aRow = wm * 64 + ((sub & 1) << 3) + lr;   // + mt*16
    int aK   = (sub >> 1) << 3;                   // + kb
    // B x2: matrices (n0-7,k0-7),(n0-7,k8-15)
    int bRow = wn * 32 + lr;                      // + nt*8
    int bK   = (sub & 1) << 3;                    // + kb

    PREFETCH(0, 0);

    for (int c = 0; c < nChunks; c++) {
        if (c + 1 < nChunks) { PREFETCH(c + 1, (c + 1) & 1); cp_wait1(); }
        else                 { cp_wait0(); }
        __syncthreads();

        uint32_t base = sb + (uint32_t)(c & 1) * 4 * TILE_B;
#pragma unroll
        for (int ks = 0; ks < 2; ks++) {
            int kb = ks * 16;
            uint32_t ah[4][4], al[4][4], bh[4][2], bl[4][2];
#pragma unroll
            for (int mt = 0; mt < 4; mt++) {
                uint32_t ao = base + (uint32_t)((aRow + mt * 16) * TS + kb + aK) * 2;
                ldm_x4(ah[mt], ao);
                ldm_x4(al[mt], ao + TILE_B);
            }
#pragma unroll
            for (int nt = 0; nt < 4; nt++) {
                uint32_t bo = base + 2 * TILE_B + (uint32_t)((bRow + nt * 8) * TS + kb + bK) * 2;
                ldm_x2(bh[nt], bo);
                ldm_x2(bl[nt], bo + TILE_B);
            }
#pragma unroll
            for (int mt = 0; mt < 4; mt++)
#pragma unroll
                for (int nt = 0; nt < 4; nt++) {
                    mma_bf16(acc[mt][nt], ah[mt], bh[nt]);
                    mma_bf16(acc[mt][nt], ah[mt], bl[nt]);
                    mma_bf16(acc[mt][nt], al[mt], bh[nt]);
                }
        }
        __syncthreads();
    }

    // epilogue: c frag lane l -> rows g=(l>>2), g+8; cols 2*(l&3), +1
    int rg = lid >> 2, cg = (lid & 3) * 2;
    float* dst = part + (size_t)z * M * Ntot;
#pragma unroll
    for (int mt = 0; mt < 4; mt++) {
        int row = m0 + wm * 64 + mt * 16 + rg;
#pragma unroll
        for (int nt = 0; nt < 4; nt++) {
            int col = n0 + wn * 32 + nt * 8 + cg;
            *(float2*)&dst[(size_t)row * Ntot + col] =
                make_float2(acc[mt][nt][0], acc[mt][nt][1]);
            *(float2*)&dst[(size_t)(row + 8) * Ntot + col] =
                make_float2(acc[mt][nt][2], acc[mt][nt][3]);
        }
    }
}

// ============================================================
// Kernel 6: combine GEMM1 split-K (Z=2) + bias + ReLU -> h hi/lo bf16
// ============================================================
__global__ void combine1(const float* __restrict__ b1) {
    int i = blockIdx.x * 256 + threadIdx.x;
    float s = g_part[i] + g_part[Bn * Hn + i] + b1[i & (Hn - 1)];
    s = fmaxf(s, 0.f);
    bf16_split(s, g_hH[i], g_hL[i]);
}

// ============================================================
// Kernel 7: combine GEMM2 split-K (Z=8) + bias b2 -> out
// ============================================================
__global__ void combine2(const float* __restrict__ b2, float* __restrict__ out) {
    int i = blockIdx.x * 256 + threadIdx.x;
    float s = b2[i & (On - 1)];
#pragma unroll
    for (int zz = 0; zz < 8; zz++) s += g_part[zz * Bn * On + i];
    out[i] = s;
}

// ============================================================
extern "C" void kernel_launch(void* const* d_in, const int* in_sizes, int n_in,
                              void* d_out, int out_size) {
    const float* x  = (const float*)d_in[0];
    const float* W1 = (const float*)d_in[1];
    const float* b1 = (const float*)d_in[2];
    const float* W2 = (const float*)d_in[3];
    const float* b2 = (const float*)d_in[4];
    const float* ic = (const float*)d_in[5];
    const float* th = (const float*)d_in[6];
    float* out = (float*)d_out;

    __nv_bfloat16 *fH, *fL, *w1h, *w1l, *w2h, *w2l, *hH, *hL;
    float* part;
    cudaGetSymbolAddress((void**)&fH,  g_fH);  cudaGetSymbolAddress((void**)&fL,  g_fL);
    cudaGetSymbolAddress((void**)&w1h, g_w1h); cudaGetSymbolAddress((void**)&w1l, g_w1l);
    cudaGetSymbolAddress((void**)&w2h, g_w2h); cudaGetSymbolAddress((void**)&w2l, g_w2l);
    cudaGetSymbolAddress((void**)&hH,  g_hH);  cudaGetSymbolAddress((void**)&hL,  g_hL);
    cudaGetSymbolAddress((void**)&part, g_part);

    const int SMEM_SZ = 2 * 4 * TILE_B;  // 81920
    cudaFuncSetAttribute(gemm_mma, cudaFuncAttributeMaxDynamicSharedMemorySize, SMEM_SZ);

    setup_kernel<<<1, 1024>>>(ic, th);
    sort_kernel<<<8, 128>>>();
    features_kernel<<<Bn, Nn>>>(x);
    conv_transpose<<<dim3(Hn / 32, Fn / 32), dim3(32, 8)>>>(W1, w1h, w1l, Fn, Hn);
    conv_transpose<<<dim3(On / 32, Hn / 32), dim3(32, 8)>>>(W2, w2h, w2l, Hn, On);
    // GEMM1: [512,1024] @ [1024,2048]^T(N-major) -> partials, Z=2 (128 CTAs)
    gemm_mma<<<dim3(Hn / 128, Bn / 128, 2), 256, SMEM_SZ>>>(fH, fL, w1h, w1l, part, Fn, Hn, Bn);
    combine1<<<(Bn * Hn) / 256, 256>>>(b1);
    // GEMM2: [512,2048] @ [2048,512]^T(N-major) -> partials, Z=8 (128 CTAs)
    gemm_mma<<<dim3(On / 128, Bn / 128, 8), 256, SMEM_SZ>>>(hH, hL, w2h, w2l, part, Hn, On, Bn);
    combine2<<<(Bn * On) / 256, 256>>>(b2, out);
}

// round 5
// speedup vs baseline: 2.4575x; 1.5835x over previous
#include <cuda_runtime.h>
#include <cuda_bf16.h>
#include <math.h>
#include <stdint.h>

#define TRAJ 1000
#define Bn 512
#define Nn 256
#define Fn 1024   // 4*N
#define Hn 2048
#define On 512

// ================= scratch (static __device__: allocation-free) =================
__device__ float g_cgt[TRAJ], g_csq[TRAJ], g_cent[TRAJ];
__device__ float g_sv[1024];
__device__ int   g_si[1024];
__device__ __nv_bfloat16 g_fH[Bn * Fn],  g_fL[Bn * Fn];    // feats hi/lo [512,1024]
__device__ __nv_bfloat16 g_w1h[Hn * Fn], g_w1l[Hn * Fn];   // W1^T hi/lo [2048,1024]
__device__ __nv_bfloat16 g_w2h[On * Hn], g_w2l[On * Hn];   // W2^T hi/lo [512,2048]
__device__ __nv_bfloat16 g_hH[Bn * Hn],  g_hL[Bn * Hn];    // h hi/lo [512,2048]
__device__ float g_part[4 * Bn * On];                      // split-K partials (Z=4)

// ================= helpers =================
__device__ __forceinline__ uint32_t smem_to_u32(const void* p) {
    uint32_t a;
    asm("{ .reg .u64 t; cvta.to.shared.u64 t, %1; cvt.u32.u64 %0, t; }" : "=r"(a) : "l"(p));
    return a;
}
__device__ __forceinline__ void cp_async16(uint32_t dst, const void* src) {
    asm volatile("cp.async.cg.shared.global [%0], [%1], 16;" :: "r"(dst), "l"(src));
}
__device__ __forceinline__ void cp_commit() { asm volatile("cp.async.commit_group;"); }
__device__ __forceinline__ void cp_wait1()  { asm volatile("cp.async.wait_group 1;"); }
__device__ __forceinline__ void cp_wait0()  { asm volatile("cp.async.wait_group 0;"); }

__device__ __forceinline__ void ldm_x4(uint32_t* r, uint32_t addr) {
    asm volatile("ldmatrix.sync.aligned.m8n8.x4.shared.b16 {%0,%1,%2,%3}, [%4];"
                 : "=r"(r[0]), "=r"(r[1]), "=r"(r[2]), "=r"(r[3]) : "r"(addr));
}
__device__ __forceinline__ void ldm_x2(uint32_t* r, uint32_t addr) {
    asm volatile("ldmatrix.sync.aligned.m8n8.x2.shared.b16 {%0,%1}, [%2];"
                 : "=r"(r[0]), "=r"(r[1]) : "r"(addr));
}
__device__ __forceinline__ void mma_bf16(float* c, const uint32_t* a, const uint32_t* b) {
    asm volatile("mma.sync.aligned.m16n8k16.row.col.f32.bf16.bf16.f32 "
                 "{%0,%1,%2,%3}, {%4,%5,%6,%7}, {%8,%9}, {%0,%1,%2,%3};"
                 : "+f"(c[0]), "+f"(c[1]), "+f"(c[2]), "+f"(c[3])
                 : "r"(a[0]), "r"(a[1]), "r"(a[2]), "r"(a[3]), "r"(b[0]), "r"(b[1]));
}
__device__ __forceinline__ void bf16_split(float v, __nv_bfloat16& h, __nv_bfloat16& l) {
    h = __float2bfloat16(v);
    l = __float2bfloat16(v - __bfloat162float(h));
}

// ============================================================
// Kernel 1: FUSED prep.
//   block 0          : serial tent map (Markstein exact division) +
//                      two-level prefix scan + bitonic rank-sort
//   blocks 1..2048   : W1 transpose + bf16 hi/lo split
//   blocks 2049..3072: W2 transpose + bf16 hi/lo split
// ============================================================
__global__ void __launch_bounds__(256)
prep_kernel(const float* __restrict__ icp, const float* __restrict__ thp,
            const float* __restrict__ W1, const float* __restrict__ W2) {
    __shared__ float tile[32][33];
    __shared__ float s_traj[TRAJ];
    __shared__ unsigned long long keys[1024];
    __shared__ float red1[256], red2[256], red3[256];

    int t = threadIdx.x;
    int bid = blockIdx.x;

    if (bid != 0) {
        // ---- weight conversion branch ----
        const float* W; __nv_bfloat16 *Th, *Tl;
        int K, N, bx, by;
        if (bid <= 2048) {
            int ti = bid - 1;            // W1: [Fn, Hn] -> T [Hn, Fn]
            W = W1; Th = g_w1h; Tl = g_w1l; K = Fn; N = Hn;
            bx = ti & 63; by = ti >> 6;  // 64 x 32 tiles
        } else {
            int ti = bid - 2049;         // W2: [Hn, On] -> T [On, Hn]
            W = W2; Th = g_w2h; Tl = g_w2l; K = Hn; N = On;
            bx = ti & 15; by = ti >> 4;  // 16 x 64 tiles
        }
        int tx = t & 31, ty = t >> 5;
        int n0 = bx * 32, k0 = by * 32;
        for (int j = ty; j < 32; j += 8)
            tile[j][tx] = W[(size_t)(k0 + j) * N + n0 + tx];
        __syncthreads();
        for (int j = ty; j < 32; j += 8) {
            float v = tile[tx][j];
            size_t o = (size_t)(n0 + j) * K + k0 + tx;
            __nv_bfloat16 h, l; bf16_split(v, h, l);
            Th[o] = h; Tl[o] = l;
        }
        return;
    }

    // ---- special block ----
    if (t == 0) {
        float thv = *thp, c = *icp;
        float omt  = __fadd_rn(1.0f, -thv);
        float rth  = __frcp_rn(thv);    // correctly-rounded reciprocals
        float romt = __frcp_rn(omt);
        s_traj[0] = c;
        for (int i = 1; i < TRAJ; i++) {
            // Markstein: q == RN(a/b) exactly, ~12 cyc vs ~45 for __fdiv_rn
            float q0 = __fmul_rn(c, rth);
            float e  = __fmaf_rn(-thv, q0, c);
            float qa = __fmaf_rn(e, rth, q0);
            float nn = __fadd_rn(1.0f, -c);
            float p0 = __fmul_rn(nn, romt);
            float f  = __fmaf_rn(-omt, p0, nn);
            float qb = __fmaf_rn(f, romt, p0);
            c = (c < thv) ? qa : qb;
            s_traj[i] = c;
        }
    }
    __syncthreads();

    // two-level exclusive prefix scan of the 3 term sequences (250 x 4 elems)
    float b1v[4], b2v[4], b3v[4];
    if (t < 250) {
        float a1 = 0.f, a2 = 0.f, a3 = 0.f;
#pragma unroll
        for (int q = 0; q < 4; q++) {
            float v = s_traj[t * 4 + q];
            b1v[q] = a1; b2v[q] = a2; b3v[q] = a3;
            a1 += (v > 0.5f) ? 1.0f : 0.0f;
            a2 += v * v;
            a3 += v * log2f(v + 1e-10f);
        }
        red1[t] = a1; red2[t] = a2; red3[t] = a3;
    }
    __syncthreads();
    if (t == 0) {
        float r1 = 0.f, r2 = 0.f, r3 = 0.f;
        for (int i = 0; i < 250; i++) {
            float x1 = red1[i], x2 = red2[i], x3 = red3[i];
            red1[i] = r1; red2[i] = r2; red3[i] = r3;
            r1 += x1; r2 += x2; r3 += x3;
        }
    }
    __syncthreads();
    if (t < 250) {
#pragma unroll
        for (int q = 0; q < 4; q++) {
            g_cgt[t * 4 + q]  = red1[t] + b1v[q];
            g_csq[t * 4 + q]  = red2[t] + b2v[q];
            g_cent[t * 4 + q] = red3[t] + b3v[q];
        }
    }

    // bitonic sort on packed (floatbits<<32 | idx) keys: stable rank order
    for (int j = t; j < 1024; j += 256) {
        unsigned long long key;
        if (j < TRAJ)
            key = ((unsigned long long)__float_as_uint(s_traj[j]) << 32) | (unsigned)j;
        else
            key = ((unsigned long long)0x7F800000u << 32) | (unsigned)j;  // +inf pad
        keys[j] = key;
    }
    __syncthreads();
    for (int k = 2; k <= 1024; k <<= 1) {
        for (int j2 = k >> 1; j2 > 0; j2 >>= 1) {
            for (int p = t; p < 1024; p += 256) {
                int l = p ^ j2;
                if (l > p) {
                    bool asc = ((p & k) == 0);
                    unsigned long long a = keys[p], b = keys[l];
                    if (asc ? (a > b) : (a < b)) { keys[p] = b; keys[l] = a; }
                }
            }
            __syncthreads();
        }
    }
    for (int j = t; j < 1024; j += 256) {
        g_sv[j] = __uint_as_float((uint32_t)(keys[j] >> 32));
        g_si[j] = (int)(uint32_t)keys[j];
    }
}

// ============================================================
// Kernel 2: features (binary-search argmin), writes bf16 hi/lo
// ============================================================
__global__ void features_kernel(const float* __restrict__ X) {
    __shared__ float s_sv[1024];
    __shared__ int   s_si[TRAJ];
    __shared__ float s_cgt[TRAJ], s_csq[TRAJ], s_cent[TRAJ];
    int tid = threadIdx.x;
    for (int j = tid; j < 1024; j += 256) s_sv[j] = g_sv[j];
    for (int j = tid; j < TRAJ; j += 256) {
        s_si[j] = g_si[j]; s_cgt[j] = g_cgt[j]; s_csq[j] = g_csq[j]; s_cent[j] = g_cent[j];
    }
    __syncthreads();

    float x = X[blockIdx.x * Nn + tid];
    int lo = 0;
#pragma unroll
    for (int step = 512; step > 0; step >>= 1)
        if (s_sv[lo + step - 1] < x) lo += step;

    const float INF = __int_as_float(0x7f800000);
    float dl = (lo > 0)    ? fabsf(x - s_sv[lo - 1]) : INF;
    float dr = (lo < TRAJ) ? fabsf(x - s_sv[lo])     : INF;
    float d = fminf(dl, dr);
    int mi = 0x7fffffff;
    if (dl == d)
        for (int k = lo - 1; k >= 0 && fabsf(x - s_sv[k]) == d; --k) mi = min(mi, s_si[k]);
    if (dr == d)
        for (int k = lo; k < TRAJ && fabsf(x - s_sv[k]) == d; ++k) mi = min(mi, s_si[k]);

    int idx = mi;
    float tt = (float)idx;
    float f[4];
    f[0] = (idx > 0) ? __fdiv_rn(s_cgt[idx], tt) : 0.0f;
    f[1] = s_csq[idx];
    f[2] = tt;
    f[3] = -s_cent[idx];
    size_t o = (size_t)blockIdx.x * Fn + tid * 4;
#pragma unroll
    for (int j = 0; j < 4; j++) bf16_split(f[j], g_fH[o + j], g_fL[o + j]);
}

// ============================================================
// Kernel 3: warp-MMA bf16 3-pass GEMM. CTA tile 128(M)x64(N), BK=32,
// 8 warps (4x2), warp tile 32x32.
//   EPI=1: epilogue fuses bias + ReLU + bf16 hi/lo split -> outH/outL
//   EPI=0: writes fp32 split-K partials -> part[z]
// ============================================================
#define TS 40                     // smem row stride (bf16 elems) = 80 B, conflict-free
#define A_T_B (128 * TS * 2)      // 10240 B per A array
#define B_T_B (64 * TS * 2)       //  5120 B per B array
#define BUF_B (2 * A_T_B + 2 * B_T_B)  // 30720 B per buffer
#define O_AH 0
#define O_AL A_T_B
#define O_BH (2 * A_T_B)
#define O_BL (2 * A_T_B + B_T_B)

template <int EPI>
__global__ void __launch_bounds__(256, 1)
gemm_mma(const __nv_bfloat16* __restrict__ Ah, const __nv_bfloat16* __restrict__ Al,
         const __nv_bfloat16* __restrict__ Bh, const __nv_bfloat16* __restrict__ Bl,
         const float* __restrict__ bias, __nv_bfloat16* __restrict__ outH,
         __nv_bfloat16* __restrict__ outL, float* __restrict__ part,
         int K, int Ntot, int M) {
    extern __shared__ char sm[];
    uint32_t sb = smem_to_u32(sm);
    int tid = threadIdx.x, wid = tid >> 5, lid = tid & 31;
    int wm = wid >> 1, wn = wid & 1;            // 4 x 2 warp grid, warp tile 32x32

    int m0 = blockIdx.y * 128, n0 = blockIdx.x * 64, z = blockIdx.z;
    int kLen = K / gridDim.z, k0 = z * kLen;
    int nChunks = kLen / 32;

    // prefetch mapping: r = tid>>2 (0..63), seg = tid&3 (16B within 64B row)
    int pr = tid >> 2, ps = tid & 3;
    uint32_t sA = (uint32_t)(pr * 80 + ps * 16);
    uint32_t sB = sA;
    size_t gA0 = ((size_t)(m0 + pr) * K + k0) * 2 + ps * 16;
    size_t gB0 = ((size_t)(n0 + pr) * K + k0) * 2 + ps * 16;
    size_t rowAdv = (size_t)64 * K * 2;

#define PREFETCH(c, b) do {                                                    \
    size_t kb = (size_t)(c) * 64;                                              \
    uint32_t base = sb + (uint32_t)(b) * BUF_B;                                \
    cp_async16(base + O_AH + sA,                (const char*)Ah + gA0 + kb);   \
    cp_async16(base + O_AH + sA + 64 * 80,      (const char*)Ah + gA0 + kb + rowAdv); \
    cp_async16(base + O_AL + sA,                (const char*)Al + gA0 + kb);   \
    cp_async16(base + O_AL + sA + 64 * 80,      (const char*)Al + gA0 + kb + rowAdv); \
    cp_async16(base + O_BH + sB,                (const char*)Bh + gB0 + kb);   \
    cp_async16(base + O_BL + sB,                (const char*)Bl + gB0 + kb);   \
    cp_commit();                                                               \
} while (0)

    float acc[2][4][4];
#pragma unroll
    for (int i = 0; i < 2; i++)
#pragma unroll
        for (int j = 0; j < 4; j++)
#pragma unroll
            for (int k = 0; k < 4; k++) acc[i][j][k] = 0.f;

    int lr = lid & 7, sub = lid >> 3;
    int aRow = wm * 32 + ((sub & 1) << 3) + lr;   // + mt*16
    int aK   = (sub >> 1) << 3;
    int bRow = wn * 32 + lr;                      // + nt*8
    int bK   = (sub & 1) << 3;

    PREFETCH(0, 0);

    for (int c = 0; c < nChunks; c++) {
        if (c + 1 < nChunks) { PREFETCH(c + 1, (c + 1) & 1); cp_wait1(); }
        else                 { cp_wait0(); }
        __syncthreads();

        uint32_t base = sb + (uint32_t)(c & 1) * BUF_B;
#pragma unroll
        for (int ks = 0; ks < 2; ks++) {
            int kb = ks * 16;
            uint32_t ah[2][4], al[2][4], bh[4][2], bl[4][2];
#pragma unroll
            for (int mt = 0; mt < 2; mt++) {
                uint32_t ao = base + (uint32_t)((aRow + mt * 16) * TS + kb + aK) * 2;
                ldm_x4(ah[mt], ao + O_AH);
                ldm_x4(al[mt], ao + O_AL);
            }
#pragma unroll
            for (int nt = 0; nt < 4; nt++) {
                uint32_t bo = base + (uint32_t)((bRow + nt * 8) * TS + kb + bK) * 2;
                ldm_x2(bh[nt], bo + O_BH);
                ldm_x2(bl[nt], bo + O_BL);
            }
#pragma unroll
            for (int mt = 0; mt < 2; mt++)
#pragma unroll
                for (int nt = 0; nt < 4; nt++) {
                    mma_bf16(acc[mt][nt], ah[mt], bh[nt]);
                    mma_bf16(acc[mt][nt], ah[mt], bl[nt]);
                    mma_bf16(acc[mt][nt], al[mt], bh[nt]);
                }
        }
        __syncthreads();
    }

    int rg = lid >> 2, cg = (lid & 3) * 2;
#pragma unroll
    for (int mt = 0; mt < 2; mt++) {
        int row = m0 + wm * 32 + mt * 16 + rg;
#pragma unroll
        for (int nt = 0; nt < 4; nt++) {
            int col = n0 + wn * 32 + nt * 8 + cg;
            if (EPI == 1) {
                float2 bi = *(const float2*)&bias[col];
#pragma unroll
                for (int hrow = 0; hrow < 2; hrow++) {
                    int r = row + hrow * 8;
                    float v0 = fmaxf(acc[mt][nt][hrow * 2 + 0] + bi.x, 0.f);
                    float v1 = fmaxf(acc[mt][nt][hrow * 2 + 1] + bi.y, 0.f);
                    __nv_bfloat16 h0, l0, h1, l1;
                    bf16_split(v0, h0, l0); bf16_split(v1, h1, l1);
                    *(__nv_bfloat162*)&outH[(size_t)r * Ntot + col] = __nv_bfloat162(h0, h1);
                    *(__nv_bfloat162*)&outL[(size_t)r * Ntot + col] = __nv_bfloat162(l0, l1);
                }
            } else {
                float* dst = part + (size_t)z * M * Ntot;
                *(float2*)&dst[(size_t)row * Ntot + col] =
                    make_float2(acc[mt][nt][0], acc[mt][nt][1]);
                *(float2*)&dst[(size_t)(row + 8) * Ntot + col] =
                    make_float2(acc[mt][nt][2], acc[mt][nt][3]);
            }
        }
    }
}

// ============================================================
// Kernel 4: combine GEMM2 split-K (Z=4) + bias b2 -> out
// ============================================================
__global__ void combine2(const float* __restrict__ b2, float* __restrict__ out) {
    int i = blockIdx.x * 256 + threadIdx.x;
    float s = b2[i & (On - 1)];
#pragma unroll
    for (int zz = 0; zz < 4; zz++) s += g_part[zz * Bn * On + i];
    out[i] = s;
}

// ============================================================
extern "C" void kernel_launch(void* const* d_in, const int* in_sizes, int n_in,
                              void* d_out, int out_size) {
    const float* x  = (const float*)d_in[0];
    const float* W1 = (const float*)d_in[1];
    const float* b1 = (const float*)d_in[2];
    const float* W2 = (const float*)d_in[3];
    const float* b2 = (const float*)d_in[4];
    const float* ic = (const float*)d_in[5];
    const float* th = (const float*)d_in[6];
    float* out = (float*)d_out;

    __nv_bfloat16 *fH, *fL, *w1h, *w1l, *w2h, *w2l, *hH, *hL;
    float* part;
    cudaGetSymbolAddress((void**)&fH,  g_fH);  cudaGetSymbolAddress((void**)&fL,  g_fL);
    cudaGetSymbolAddress((void**)&w1h, g_w1h); cudaGetSymbolAddress((void**)&w1l, g_w1l);
    cudaGetSymbolAddress((void**)&w2h, g_w2h); cudaGetSymbolAddress((void**)&w2l, g_w2l);
    cudaGetSymbolAddress((void**)&hH,  g_hH);  cudaGetSymbolAddress((void**)&hL,  g_hL);
    cudaGetSymbolAddress((void**)&part, g_part);

    const int SMEM_SZ = 2 * BUF_B;  // 61440
    cudaFuncSetAttribute(gemm_mma<1>, cudaFuncAttributeMaxDynamicSharedMemorySize, SMEM_SZ);
    cudaFuncSetAttribute(gemm_mma<0>, cudaFuncAttributeMaxDynamicSharedMemorySize, SMEM_SZ);

    // fused: serial trajectory/scan/sort (block 0) || W1/W2 convert (3072 blocks)
    prep_kernel<<<3073, 256>>>(ic, th, W1, W2);
    features_kernel<<<Bn, Nn>>>(x);
    // GEMM1: [512,1024]x[1024,2048], Z=1, fused bias+relu+split -> h  (128 CTAs)
    gemm_mma<1><<<dim3(Hn / 64, Bn / 128, 1), 256, SMEM_SZ>>>(
        fH, fL, w1h, w1l, b1, hH, hL, nullptr, Fn, Hn, Bn);
    // GEMM2: [512,2048]x[2048,512], Z=4 -> partials  (128 CTAs)
    gemm_mma<0><<<dim3(On / 64, Bn / 128, 4), 256, SMEM_SZ>>>(
        hH, hL, w2h, w2l, nullptr, nullptr, nullptr, part, Hn, On, Bn);
    combine2<<<(Bn * On) / 256, 256>>>(b2, out);
}